// round 15
// baseline (speedup 1.0000x reference)
#include <cuda_runtime.h>
#include <cuda_bf16.h>
#include <cstdint>

#define B_   2
#define S_   4096
#define D_   768
#define H_   12
#define DH_  64
#define W_   256

typedef unsigned long long ull;

// ------------------------------ device scratch ------------------------------
__device__ __align__(128) float g_q[(size_t)B_ * H_ * S_ * DH_];
__device__ __align__(128) float g_k[(size_t)B_ * H_ * S_ * DH_];
__device__ __align__(128) float g_v[(size_t)B_ * H_ * S_ * DH_];

__device__ __align__(128) __nv_bfloat16 g_Ah[(size_t)B_ * S_ * D_];
__device__ __align__(128) __nv_bfloat16 g_Al[(size_t)B_ * S_ * D_];
__device__ __align__(128) __nv_bfloat16 g_Wth[3 * D_ * D_];   // W^T hi  [n][k]
__device__ __align__(128) __nv_bfloat16 g_Wtl[3 * D_ * D_];   // W^T lo

// ------------------------------ PTX helpers --------------------------------
__device__ __forceinline__ uint32_t smem_u32(const void* p) {
    uint32_t a;
    asm("{ .reg .u64 t; cvta.to.shared.u64 t, %1; cvt.u32.u64 %0, t; }"
        : "=r"(a) : "l"(p));
    return a;
}

#define CP_ASYNC16(dst, src) \
    asm volatile("cp.async.cg.shared.global [%0], [%1], 16;" \
                 :: "r"(dst), "l"(src) : "memory")
#define CP_COMMIT() asm volatile("cp.async.commit_group;" ::: "memory")
#define CP_WAIT0()  asm volatile("cp.async.wait_group 0;" ::: "memory")
#define CP_WAIT1()  asm volatile("cp.async.wait_group 1;" ::: "memory")

#define LDSM4(r, a) \
    asm volatile("ldmatrix.sync.aligned.m8n8.x4.shared.b16 {%0,%1,%2,%3}, [%4];" \
                 : "=r"((r)[0]), "=r"((r)[1]), "=r"((r)[2]), "=r"((r)[3]) : "r"(a))

#define MMA16816(d, a, b) \
    asm volatile("mma.sync.aligned.m16n8k16.row.col.f32.bf16.bf16.f32 " \
                 "{%0,%1,%2,%3}, {%4,%5,%6,%7}, {%8,%9}, {%0,%1,%2,%3};" \
                 : "+f"((d)[0]), "+f"((d)[1]), "+f"((d)[2]), "+f"((d)[3]) \
                 : "r"((a)[0]), "r"((a)[1]), "r"((a)[2]), "r"((a)[3]), \
                   "r"((b)[0]), "r"((b)[1]))

// =========================== convert: A -> hi/lo bf16 ========================
__global__ __launch_bounds__(256)
void conv_a_kernel(const float* __restrict__ A)
{
    size_t i = ((size_t)blockIdx.x * 256 + threadIdx.x) * 4;
    float4 v = *(const float4*)&A[i];
    __nv_bfloat16 h0 = __float2bfloat16(v.x);
    __nv_bfloat16 h1 = __float2bfloat16(v.y);
    __nv_bfloat16 h2 = __float2bfloat16(v.z);
    __nv_bfloat16 h3 = __float2bfloat16(v.w);
    __nv_bfloat16 l0 = __float2bfloat16(v.x - __bfloat162float(h0));
    __nv_bfloat16 l1 = __float2bfloat16(v.y - __bfloat162float(h1));
    __nv_bfloat16 l2 = __float2bfloat16(v.z - __bfloat162float(h2));
    __nv_bfloat16 l3 = __float2bfloat16(v.w - __bfloat162float(h3));
    *(__nv_bfloat162*)&g_Ah[i]     = __nv_bfloat162(h0, h1);
    *(__nv_bfloat162*)&g_Ah[i + 2] = __nv_bfloat162(h2, h3);
    *(__nv_bfloat162*)&g_Al[i]     = __nv_bfloat162(l0, l1);
    *(__nv_bfloat162*)&g_Al[i + 2] = __nv_bfloat162(l2, l3);
}

// ==================== convert: W -> W^T hi/lo bf16 (tiled) ===================
__global__ __launch_bounds__(256)
void conv_wt_kernel(const float* __restrict__ Wq, const float* __restrict__ Wk,
                    const float* __restrict__ Wv)
{
    __shared__ float t[32][33];
    const int z = blockIdx.z;
    const float* Wm = (z == 0) ? Wq : (z == 1) ? Wk : Wv;
    const int n0 = blockIdx.x * 32, k0 = blockIdx.y * 32;
    const int tx = threadIdx.x, ty = threadIdx.y;   // (32, 8)
#pragma unroll
    for (int j = 0; j < 4; j++)
        t[ty + 8 * j][tx] = Wm[(size_t)(k0 + ty + 8 * j) * D_ + n0 + tx];
    __syncthreads();
    size_t base = (size_t)z * D_ * D_;
#pragma unroll
    for (int j = 0; j < 4; j++) {
        int n = n0 + ty + 8 * j, k = k0 + tx;
        float x = t[tx][ty + 8 * j];
        __nv_bfloat16 hi = __float2bfloat16(x);
        __nv_bfloat16 lo = __float2bfloat16(x - __bfloat162float(hi));
        g_Wth[base + (size_t)n * D_ + k] = hi;
        g_Wtl[base + (size_t)n * D_ + k] = lo;
    }
}

// ================= warp-MMA split-bf16 projection GEMM ======================
// CTA tile M=128, N=128; K=768 in 12 panels of 64; cp.async double buffer.
// smem tile: [128 rows][72 bf16] (144B rows -> ldmatrix conflict-free).
#define TILE_B   18432              // 128*72*2
#define BUF_B    (4 * TILE_B)       // Ah, Al, Bh, Bl
#define SM_GEMM  (2 * BUF_B)        // 147456

__global__ __launch_bounds__(256, 1)
void mma_gemm_kernel(const float* __restrict__ bq, const float* __restrict__ bk,
                     const float* __restrict__ bv)
{
    extern __shared__ char sm[];
    const uint32_t smb = smem_u32(sm);
    const int tid  = threadIdx.x;
    const int wid  = tid >> 5, lane = tid & 31;
    const int wm   = wid & 3,  wn   = wid >> 2;     // warp grid 4 x 2
    const int n0   = blockIdx.x * 128;
    const int m0   = blockIdx.y * 128;
    const int z    = blockIdx.z;

    const __nv_bfloat16* __restrict__ Wth = g_Wth + (size_t)z * D_ * D_;
    const __nv_bfloat16* __restrict__ Wtl = g_Wtl + (size_t)z * D_ * D_;

    // per-thread cp.async source/dest pattern (16 loads / panel)
    // idx = it*256+tid : row = idx>>3, col = (idx&7)*8
    // ldmatrix per-lane offsets (bytes, within a tile)
    const uint32_t a_off = (uint32_t)((wm * 32 + (lane & 15)) * 144 +
                                      ((lane >> 4) << 4));
    const uint32_t b_off = (uint32_t)((wn * 64 + ((lane >> 4) << 3) + (lane & 7)) * 144 +
                                      ((lane & 8) << 1));

    float acc[2][8][4];
#pragma unroll
    for (int mi = 0; mi < 2; mi++)
#pragma unroll
        for (int ni = 0; ni < 8; ni++)
#pragma unroll
            for (int r = 0; r < 4; r++) acc[mi][ni][r] = 0.f;

    // ---- prologue: load panel 0 into buffer 0 ----
#pragma unroll
    for (int it = 0; it < 4; it++) {
        int idx = it * 256 + tid;
        int r = idx >> 3, c = (idx & 7) * 8;
        uint32_t so = (uint32_t)(r * 144 + c * 2);
        size_t ga = (size_t)(m0 + r) * D_ + c;
        size_t gb = (size_t)(n0 + r) * D_ + c;
        CP_ASYNC16(smb + 0 * TILE_B + so, (const char*)&g_Ah[ga]);
        CP_ASYNC16(smb + 1 * TILE_B + so, (const char*)&g_Al[ga]);
        CP_ASYNC16(smb + 2 * TILE_B + so, (const char*)&Wth[gb]);
        CP_ASYNC16(smb + 3 * TILE_B + so, (const char*)&Wtl[gb]);
    }
    CP_COMMIT();

    for (int p = 0; p < 12; p++) {
        const uint32_t buf = smb + (p & 1) * BUF_B;
        // kick off next panel into the other buffer
        if (p < 11) {
            const uint32_t nb = smb + ((p + 1) & 1) * BUF_B;
            const int kt = (p + 1) * 64;
#pragma unroll
            for (int it = 0; it < 4; it++) {
                int idx = it * 256 + tid;
                int r = idx >> 3, c = (idx & 7) * 8;
                uint32_t so = (uint32_t)(r * 144 + c * 2);
                size_t ga = (size_t)(m0 + r) * D_ + kt + c;
                size_t gb = (size_t)(n0 + r) * D_ + kt + c;
                CP_ASYNC16(nb + 0 * TILE_B + so, (const char*)&g_Ah[ga]);
                CP_ASYNC16(nb + 1 * TILE_B + so, (const char*)&g_Al[ga]);
                CP_ASYNC16(nb + 2 * TILE_B + so, (const char*)&Wth[gb]);
                CP_ASYNC16(nb + 3 * TILE_B + so, (const char*)&Wtl[gb]);
            }
            CP_COMMIT();
            CP_WAIT1();           // panel p finished, p+1 in flight
        } else {
            CP_WAIT0();
        }
        __syncthreads();

        // ---- compute on buffer p ----
#pragma unroll
        for (int kk = 0; kk < 4; kk++) {
            const uint32_t kb = kk * 32;
            uint32_t ah[2][4], al[2][4];
#pragma unroll
            for (int mi = 0; mi < 2; mi++) {
                LDSM4(ah[mi], buf + 0 * TILE_B + a_off + mi * 2304 + kb);
                LDSM4(al[mi], buf + 1 * TILE_B + a_off + mi * 2304 + kb);
            }
            uint32_t bh[8][2], bl[8][2];
#pragma unroll
            for (int nq = 0; nq < 4; nq++) {
                uint32_t t4[4];
                LDSM4(t4, buf + 2 * TILE_B + b_off + nq * 2304 + kb);
                bh[2 * nq][0] = t4[0]; bh[2 * nq][1] = t4[1];
                bh[2 * nq + 1][0] = t4[2]; bh[2 * nq + 1][1] = t4[3];
                LDSM4(t4, buf + 3 * TILE_B + b_off + nq * 2304 + kb);
                bl[2 * nq][0] = t4[0]; bl[2 * nq][1] = t4[1];
                bl[2 * nq + 1][0] = t4[2]; bl[2 * nq + 1][1] = t4[3];
            }
#pragma unroll
            for (int mi = 0; mi < 2; mi++)
#pragma unroll
                for (int nj = 0; nj < 8; nj++) {
                    MMA16816(acc[mi][nj], ah[mi], bh[nj]);
                    MMA16816(acc[mi][nj], ah[mi], bl[nj]);
                    MMA16816(acc[mi][nj], al[mi], bh[nj]);
                }
        }
        __syncthreads();
    }

    // ---- epilogue: bias + scale, scatter to [B,H,S,64] ----
    const float* bias = (z == 0) ? bq : (z == 1) ? bk : bv;
    float* dst = (z == 0) ? g_q : (z == 1) ? g_k : g_v;
    const float scale = (z == 0) ? 0.125f : 1.0f;
    const int group = lane >> 2, tig = lane & 3;
    const int hh = (n0 + wn * 64) >> 6;                 // head constant per warp
#pragma unroll
    for (int mi = 0; mi < 2; mi++) {
#pragma unroll
        for (int hf = 0; hf < 2; hf++) {
            int m = m0 + wm * 32 + mi * 16 + group + hf * 8;
            int bb = m >> 12, srow = m & (S_ - 1);
            float* o = dst + (((size_t)bb * H_ + hh) * S_ + srow) * DH_;
#pragma unroll
            for (int ni = 0; ni < 8; ni++) {
                int dc = ni * 8 + tig * 2;
                int ng = n0 + wn * 64 + dc;
                float2 w;
                w.x = (acc[mi][ni][2 * hf + 0] + bias[ng])     * scale;
                w.y = (acc[mi][ni][2 * hf + 1] + bias[ng + 1]) * scale;
                *(float2*)&o[dc] = w;
            }
        }
    }
}

// ============================ fp32 helpers (attn) ============================
__device__ __forceinline__ ull pack2(float lo, float hi) {
    ull r; asm("mov.b64 %0, {%1,%2};" : "=l"(r) : "f"(lo), "f"(hi)); return r;
}
__device__ __forceinline__ float2 unpack2(ull u) {
    float2 r; asm("mov.b64 {%0,%1}, %2;" : "=f"(r.x), "=f"(r.y) : "l"(u)); return r;
}
__device__ __forceinline__ void fma2(ull& d, ull a, ull b) {
    asm("fma.rn.f32x2 %0, %1, %2, %0;" : "+l"(d) : "l"(a), "l"(b));
}
__device__ __forceinline__ void mul2(ull& d, ull a) {
    asm("mul.rn.f32x2 %0, %0, %1;" : "+l"(d) : "l"(a));
}
#define NEG_INF (__int_as_float(0xff800000))

// ============================ Banded attention ===============================
#define SMEM_ATTN 204800

__global__ __launch_bounds__(256, 1)
void attn_kernel(const float* __restrict__ att_mask,
                 const unsigned char* __restrict__ idx_mask,
                 float* __restrict__ out)
{
    extern __shared__ char smraw[];
    ull*   Qt2  = (ull*)  (smraw);            // [64][130] dup pairs (d-major)
    float* Kt   = (float*)(smraw + 66560);    // [64][132] (d-major)
    float* Vs   = (float*)(smraw + 100352);   // [128][68] (k-major)
    float* Ps   = (float*)(smraw + 135168);   // [128][132]
    float* fm_s = (float*)(smraw + 202752);   // [128]
    float* m_s  = (float*)(smraw + 203264);
    float* l_s  = (float*)(smraw + 203776);
    float* sc_s = (float*)(smraw + 204288);

    const int tid = threadIdx.x;
    const int tx = tid & 15, ty = tid >> 4;
    const int q0 = blockIdx.x * 128;
    const int b  = blockIdx.y / H_;
    const int h  = blockIdx.y % H_;
    const size_t bh = ((size_t)b * H_ + h) * (size_t)S_ * DH_;

#pragma unroll
    for (int it = 0; it < 8; it++) {
        int idx = it * 256 + tid;
        int qr = idx >> 4, c4 = (idx & 15) * 4;
        float4 v = *(const float4*)&g_q[bh + (size_t)(q0 + qr) * DH_ + c4];
        Qt2[(c4 + 0) * 130 + qr] = pack2(v.x, v.x);
        Qt2[(c4 + 1) * 130 + qr] = pack2(v.y, v.y);
        Qt2[(c4 + 2) * 130 + qr] = pack2(v.z, v.z);
        Qt2[(c4 + 3) * 130 + qr] = pack2(v.w, v.w);
    }
    if (tid < 128) { m_s[tid] = NEG_INF; l_s[tid] = 0.f; }

    ull o2[8][2];
#pragma unroll
    for (int i = 0; i < 8; i++) { o2[i][0] = 0ULL; o2[i][1] = 0ULL; }

    for (int c = 0; c < 5; c++) {
        const int kstart = q0 - 256 + c * 128;
        __syncthreads();

#pragma unroll
        for (int it = 0; it < 8; it++) {
            int idx = it * 256 + tid;
            int kr = idx >> 4, c4 = (idx & 15) * 4;
            int kg = kstart + kr;
            float4 kv = make_float4(0.f, 0.f, 0.f, 0.f);
            float4 vv = make_float4(0.f, 0.f, 0.f, 0.f);
            if ((unsigned)kg < (unsigned)S_) {
                kv = *(const float4*)&g_k[bh + (size_t)kg * DH_ + c4];
                vv = *(const float4*)&g_v[bh + (size_t)kg * DH_ + c4];
            }
            Kt[(c4 + 0) * 132 + kr] = kv.x;
            Kt[(c4 + 1) * 132 + kr] = kv.y;
            Kt[(c4 + 2) * 132 + kr] = kv.z;
            Kt[(c4 + 3) * 132 + kr] = kv.w;
            *(float4*)&Vs[kr * 68 + c4] = vv;
        }
        if (tid < 128) {
            int kg = kstart + tid;
            float fv = NEG_INF;
            if ((unsigned)kg < (unsigned)S_)
                fv = (att_mask[(size_t)b * S_ + kg] != 0.f) ? NEG_INF : 0.f;
            fm_s[tid] = fv;
        }
        __syncthreads();

        // ---- score GEMM ----
        {
            ull sacc[8][4];
#pragma unroll
            for (int i = 0; i < 8; i++)
#pragma unroll
                for (int j = 0; j < 4; j++) sacc[i][j] = 0ULL;

#pragma unroll 16
            for (int d = 0; d < 64; d++) {
                const ulonglong2* pa = (const ulonglong2*)&Qt2[d * 130 + ty * 8];
                ulonglong2 a01 = pa[0], a23 = pa[1], a45 = pa[2], a67 = pa[3];
                const ulonglong2* pb = (const ulonglong2*)&Kt[d * 132 + tx * 8];
                ulonglong2 b01 = pb[0], b23 = pb[1];
                ull av[8] = {a01.x, a01.y, a23.x, a23.y, a45.x, a45.y, a67.x, a67.y};
#pragma unroll
                for (int i = 0; i < 8; i++) {
                    fma2(sacc[i][0], av[i], b01.x);
                    fma2(sacc[i][1], av[i], b01.y);
                    fma2(sacc[i][2], av[i], b23.x);
                    fma2(sacc[i][3], av[i], b23.y);
                }
            }
#pragma unroll
            for (int i = 0; i < 8; i++) {
                float2 s0 = unpack2(sacc[i][0]), s1 = unpack2(sacc[i][1]);
                float2 s2 = unpack2(sacc[i][2]), s3 = unpack2(sacc[i][3]);
                int r = ty * 8 + i, cc = tx * 8;
                *(float4*)&Ps[r * 132 + cc]     = make_float4(s0.x, s0.y, s1.x, s1.y);
                *(float4*)&Ps[r * 132 + cc + 4] = make_float4(s2.x, s2.y, s3.x, s3.y);
            }
        }
        __syncthreads();

        // ---- online softmax: 2 threads per row ----
        {
            int r = tid >> 1, half = tid & 1, cb = half * 64;
            int boff = kstart - q0 + cb - r;
            float mx = NEG_INF;
#pragma unroll
            for (int t = 0; t < 16; t++) {
                float4 sv = *(const float4*)&Ps[r * 132 + cb + t * 4];
                int cc = t * 4; float s;
                s = sv.x + fm_s[cb + cc + 0]; if ((unsigned)(boff + cc + 0 + W_) > 2u * W_) s = NEG_INF; mx = fmaxf(mx, s);
                s = sv.y + fm_s[cb + cc + 1]; if ((unsigned)(boff + cc + 1 + W_) > 2u * W_) s = NEG_INF; mx = fmaxf(mx, s);
                s = sv.z + fm_s[cb + cc + 2]; if ((unsigned)(boff + cc + 2 + W_) > 2u * W_) s = NEG_INF; mx = fmaxf(mx, s);
                s = sv.w + fm_s[cb + cc + 3]; if ((unsigned)(boff + cc + 3 + W_) > 2u * W_) s = NEG_INF; mx = fmaxf(mx, s);
            }
            mx = fmaxf(mx, __shfl_xor_sync(0xffffffffu, mx, 1));
            float m_old = m_s[r];
            float m_new = fmaxf(m_old, mx);
            float scal, mref;
            if (m_new == NEG_INF) { scal = 1.f; mref = 0.f; }
            else                  { scal = __expf(m_old - m_new); mref = m_new; }
            float lsum = 0.f;
#pragma unroll
            for (int t = 0; t < 16; t++) {
                float4 sv = *(float4*)&Ps[r * 132 + cb + t * 4];
                int cc = t * 4; float s, p;
                s = sv.x + fm_s[cb + cc + 0]; if ((unsigned)(boff + cc + 0 + W_) > 2u * W_) s = NEG_INF;
                p = __expf(s - mref); lsum += p; sv.x = p;
                s = sv.y + fm_s[cb + cc + 1]; if ((unsigned)(boff + cc + 1 + W_) > 2u * W_) s = NEG_INF;
                p = __expf(s - mref); lsum += p; sv.y = p;
                s = sv.z + fm_s[cb + cc + 2]; if ((unsigned)(boff + cc + 2 + W_) > 2u * W_) s = NEG_INF;
                p = __expf(s - mref); lsum += p; sv.z = p;
                s = sv.w + fm_s[cb + cc + 3]; if ((unsigned)(boff + cc + 3 + W_) > 2u * W_) s = NEG_INF;
                p = __expf(s - mref); lsum += p; sv.w = p;
                *(float4*)&Ps[r * 132 + cb + t * 4] = sv;
            }
            lsum += __shfl_xor_sync(0xffffffffu, lsum, 1);
            if (half == 0) {
                m_s[r]  = m_new;
                l_s[r]  = l_s[r] * scal + lsum;
                sc_s[r] = scal;
            }
        }
        __syncthreads();

        // ---- rescale + P @ V ----
#pragma unroll
        for (int i = 0; i < 8; i++) {
            float sc = sc_s[ty * 8 + i];
            ull sp = pack2(sc, sc);
            mul2(o2[i][0], sp);
            mul2(o2[i][1], sp);
        }
#pragma unroll 8
        for (int k = 0; k < 128; k++) {
            ulonglong2 vv = *(const ulonglong2*)&Vs[k * 68 + tx * 4];
#pragma unroll
            for (int i = 0; i < 8; i++) {
                float p = Ps[(ty * 8 + i) * 132 + k];
                ull pp = pack2(p, p);
                fma2(o2[i][0], pp, vv.x);
                fma2(o2[i][1], pp, vv.y);
            }
        }
    }

    // ---- epilogue ----
#pragma unroll
    for (int i = 0; i < 8; i++) {
        int r  = ty * 8 + i;
        int qg = q0 + r;
        float inv = 1.f / fmaxf(l_s[r], 1e-37f);
        if (idx_mask[(size_t)b * S_ + qg]) inv = 0.f;
        float2 f0 = unpack2(o2[i][0]);
        float2 f1 = unpack2(o2[i][1]);
        float4 o = make_float4(f0.x * inv, f0.y * inv, f1.x * inv, f1.y * inv);
        *(float4*)&out[((size_t)b * S_ + qg) * D_ + h * DH_ + tx * 4] = o;
    }
}

// =============================================================================
extern "C" void kernel_launch(void* const* d_in, const int* in_sizes, int n_in,
                              void* d_out, int out_size)
{
    const float*         hidden = (const float*)d_in[0];
    const float*         amask  = (const float*)d_in[1];
    const unsigned char* imask  = (const unsigned char*)d_in[2];
    const float* Wq = (const float*)d_in[3];
    const float* bq = (const float*)d_in[4];
    const float* Wk = (const float*)d_in[5];
    const float* bk = (const float*)d_in[6];
    const float* Wv = (const float*)d_in[7];
    const float* bv = (const float*)d_in[8];
    float* out = (float*)d_out;

    cudaFuncSetAttribute(mma_gemm_kernel,
                         cudaFuncAttributeMaxDynamicSharedMemorySize, SM_GEMM);
    cudaFuncSetAttribute(attn_kernel,
                         cudaFuncAttributeMaxDynamicSharedMemorySize, SMEM_ATTN);

    // 1) split-bf16 conversions
    conv_a_kernel<<<(B_ * S_ * D_) / (256 * 4), 256>>>(hidden);
    conv_wt_kernel<<<dim3(D_ / 32, D_ / 32, 3), dim3(32, 8)>>>(Wq, Wk, Wv);

    // 2) warp-MMA projections (Q, K, V via blockIdx.z)
    mma_gemm_kernel<<<dim3(D_ / 128, (B_ * S_) / 128, 3), 256, SM_GEMM>>>(bq, bk, bv);

    // 3) banded attention
    attn_kernel<<<dim3(S_ / 128, B_ * H_), 256, SMEM_ATTN>>>(amask, imask, out);
}

// round 16
// speedup vs baseline: 1.0007x; 1.0007x over previous
#include <cuda_runtime.h>
#include <cuda_bf16.h>
#include <cstdint>

#define B_   2
#define S_   4096
#define D_   768
#define H_   12
#define DH_  64
#define W_   256

typedef unsigned long long ull;

// ------------------------------ device scratch ------------------------------
__device__ __align__(128) float g_q[(size_t)B_ * H_ * S_ * DH_];
__device__ __align__(128) float g_k[(size_t)B_ * H_ * S_ * DH_];
__device__ __align__(128) float g_v[(size_t)B_ * H_ * S_ * DH_];

__device__ __align__(128) __nv_bfloat16 g_Ah[(size_t)B_ * S_ * D_];
__device__ __align__(128) __nv_bfloat16 g_Al[(size_t)B_ * S_ * D_];
__device__ __align__(128) __nv_bfloat16 g_Wth[3 * D_ * D_];   // W^T hi  [n][k]
__device__ __align__(128) __nv_bfloat16 g_Wtl[3 * D_ * D_];   // W^T lo

// ------------------------------ PTX helpers --------------------------------
__device__ __forceinline__ uint32_t smem_u32(const void* p) {
    uint32_t a;
    asm("{ .reg .u64 t; cvta.to.shared.u64 t, %1; cvt.u32.u64 %0, t; }"
        : "=r"(a) : "l"(p));
    return a;
}

#define CP_ASYNC16(dst, src) \
    asm volatile("cp.async.cg.shared.global [%0], [%1], 16;" \
                 :: "r"(dst), "l"(src) : "memory")
#define CP_COMMIT() asm volatile("cp.async.commit_group;" ::: "memory")
#define CP_WAIT0()  asm volatile("cp.async.wait_group 0;" ::: "memory")
#define CP_WAIT1()  asm volatile("cp.async.wait_group 1;" ::: "memory")

#define LDSM4(r, a) \
    asm volatile("ldmatrix.sync.aligned.m8n8.x4.shared.b16 {%0,%1,%2,%3}, [%4];" \
                 : "=r"((r)[0]), "=r"((r)[1]), "=r"((r)[2]), "=r"((r)[3]) : "r"(a))

#define MMA16816(d, a, b) \
    asm volatile("mma.sync.aligned.m16n8k16.row.col.f32.bf16.bf16.f32 " \
                 "{%0,%1,%2,%3}, {%4,%5,%6,%7}, {%8,%9}, {%0,%1,%2,%3};" \
                 : "+f"((d)[0]), "+f"((d)[1]), "+f"((d)[2]), "+f"((d)[3]) \
                 : "r"((a)[0]), "r"((a)[1]), "r"((a)[2]), "r"((a)[3]), \
                   "r"((b)[0]), "r"((b)[1]))

// =========================== convert: A -> hi/lo bf16 ========================
__global__ __launch_bounds__(256)
void conv_a_kernel(const float* __restrict__ A)
{
    size_t i = ((size_t)blockIdx.x * 256 + threadIdx.x) * 4;
    float4 v = *(const float4*)&A[i];
    __nv_bfloat16 h0 = __float2bfloat16(v.x);
    __nv_bfloat16 h1 = __float2bfloat16(v.y);
    __nv_bfloat16 h2 = __float2bfloat16(v.z);
    __nv_bfloat16 h3 = __float2bfloat16(v.w);
    __nv_bfloat16 l0 = __float2bfloat16(v.x - __bfloat162float(h0));
    __nv_bfloat16 l1 = __float2bfloat16(v.y - __bfloat162float(h1));
    __nv_bfloat16 l2 = __float2bfloat16(v.z - __bfloat162float(h2));
    __nv_bfloat16 l3 = __float2bfloat16(v.w - __bfloat162float(h3));
    *(__nv_bfloat162*)&g_Ah[i]     = __nv_bfloat162(h0, h1);
    *(__nv_bfloat162*)&g_Ah[i + 2] = __nv_bfloat162(h2, h3);
    *(__nv_bfloat162*)&g_Al[i]     = __nv_bfloat162(l0, l1);
    *(__nv_bfloat162*)&g_Al[i + 2] = __nv_bfloat162(l2, l3);
}

// ==================== convert: W -> W^T hi/lo bf16 (tiled) ===================
__global__ __launch_bounds__(256)
void conv_wt_kernel(const float* __restrict__ Wq, const float* __restrict__ Wk,
                    const float* __restrict__ Wv)
{
    __shared__ float t[32][33];
    const int z = blockIdx.z;
    const float* Wm = (z == 0) ? Wq : (z == 1) ? Wk : Wv;
    const int n0 = blockIdx.x * 32, k0 = blockIdx.y * 32;
    const int tx = threadIdx.x, ty = threadIdx.y;   // (32, 8)
#pragma unroll
    for (int j = 0; j < 4; j++)
        t[ty + 8 * j][tx] = Wm[(size_t)(k0 + ty + 8 * j) * D_ + n0 + tx];
    __syncthreads();
    size_t base = (size_t)z * D_ * D_;
#pragma unroll
    for (int j = 0; j < 4; j++) {
        int n = n0 + ty + 8 * j, k = k0 + tx;
        float x = t[tx][ty + 8 * j];
        __nv_bfloat16 hi = __float2bfloat16(x);
        __nv_bfloat16 lo = __float2bfloat16(x - __bfloat162float(hi));
        g_Wth[base + (size_t)n * D_ + k] = hi;
        g_Wtl[base + (size_t)n * D_ + k] = lo;
    }
}

// ================= warp-MMA split-bf16 projection GEMM ======================
// CTA tile M=128, N=128; K=768 in 12 panels of 64; cp.async double buffer.
// smem tile: [128 rows][72 bf16] (144B rows -> ldmatrix conflict-free).
#define TILE_B   18432              // 128*72*2
#define BUF_B    (4 * TILE_B)       // Ah, Al, Bh, Bl
#define SM_GEMM  (2 * BUF_B)        // 147456

__global__ __launch_bounds__(256, 1)
void mma_gemm_kernel(const float* __restrict__ bq, const float* __restrict__ bk,
                     const float* __restrict__ bv)
{
    extern __shared__ char sm[];
    const uint32_t smb = smem_u32(sm);
    const int tid  = threadIdx.x;
    const int wid  = tid >> 5, lane = tid & 31;
    const int wm   = wid & 3,  wn   = wid >> 2;     // warp grid 4 x 2
    const int n0   = blockIdx.x * 128;
    const int m0   = blockIdx.y * 128;
    const int z    = blockIdx.z;

    const __nv_bfloat16* __restrict__ Wth = g_Wth + (size_t)z * D_ * D_;
    const __nv_bfloat16* __restrict__ Wtl = g_Wtl + (size_t)z * D_ * D_;

    // per-thread cp.async source/dest pattern (16 loads / panel)
    // idx = it*256+tid : row = idx>>3, col = (idx&7)*8
    // ldmatrix per-lane offsets (bytes, within a tile)
    const uint32_t a_off = (uint32_t)((wm * 32 + (lane & 15)) * 144 +
                                      ((lane >> 4) << 4));
    const uint32_t b_off = (uint32_t)((wn * 64 + ((lane >> 4) << 3) + (lane & 7)) * 144 +
                                      ((lane & 8) << 1));

    float acc[2][8][4];
#pragma unroll
    for (int mi = 0; mi < 2; mi++)
#pragma unroll
        for (int ni = 0; ni < 8; ni++)
#pragma unroll
            for (int r = 0; r < 4; r++) acc[mi][ni][r] = 0.f;

    // ---- prologue: load panel 0 into buffer 0 ----
#pragma unroll
    for (int it = 0; it < 4; it++) {
        int idx = it * 256 + tid;
        int r = idx >> 3, c = (idx & 7) * 8;
        uint32_t so = (uint32_t)(r * 144 + c * 2);
        size_t ga = (size_t)(m0 + r) * D_ + c;
        size_t gb = (size_t)(n0 + r) * D_ + c;
        CP_ASYNC16(smb + 0 * TILE_B + so, (const char*)&g_Ah[ga]);
        CP_ASYNC16(smb + 1 * TILE_B + so, (const char*)&g_Al[ga]);
        CP_ASYNC16(smb + 2 * TILE_B + so, (const char*)&Wth[gb]);
        CP_ASYNC16(smb + 3 * TILE_B + so, (const char*)&Wtl[gb]);
    }
    CP_COMMIT();

    for (int p = 0; p < 12; p++) {
        const uint32_t buf = smb + (p & 1) * BUF_B;
        // kick off next panel into the other buffer
        if (p < 11) {
            const uint32_t nb = smb + ((p + 1) & 1) * BUF_B;
            const int kt = (p + 1) * 64;
#pragma unroll
            for (int it = 0; it < 4; it++) {
                int idx = it * 256 + tid;
                int r = idx >> 3, c = (idx & 7) * 8;
                uint32_t so = (uint32_t)(r * 144 + c * 2);
                size_t ga = (size_t)(m0 + r) * D_ + kt + c;
                size_t gb = (size_t)(n0 + r) * D_ + kt + c;
                CP_ASYNC16(nb + 0 * TILE_B + so, (const char*)&g_Ah[ga]);
                CP_ASYNC16(nb + 1 * TILE_B + so, (const char*)&g_Al[ga]);
                CP_ASYNC16(nb + 2 * TILE_B + so, (const char*)&Wth[gb]);
                CP_ASYNC16(nb + 3 * TILE_B + so, (const char*)&Wtl[gb]);
            }
            CP_COMMIT();
            CP_WAIT1();           // panel p finished, p+1 in flight
        } else {
            CP_WAIT0();
        }
        __syncthreads();

        // ---- compute on buffer p ----
#pragma unroll
        for (int kk = 0; kk < 4; kk++) {
            const uint32_t kb = kk * 32;
            uint32_t ah[2][4], al[2][4];
#pragma unroll
            for (int mi = 0; mi < 2; mi++) {
                LDSM4(ah[mi], buf + 0 * TILE_B + a_off + mi * 2304 + kb);
                LDSM4(al[mi], buf + 1 * TILE_B + a_off + mi * 2304 + kb);
            }
            uint32_t bh[8][2], bl[8][2];
#pragma unroll
            for (int nq = 0; nq < 4; nq++) {
                uint32_t t4[4];
                LDSM4(t4, buf + 2 * TILE_B + b_off + nq * 2304 + kb);
                bh[2 * nq][0] = t4[0]; bh[2 * nq][1] = t4[1];
                bh[2 * nq + 1][0] = t4[2]; bh[2 * nq + 1][1] = t4[3];
                LDSM4(t4, buf + 3 * TILE_B + b_off + nq * 2304 + kb);
                bl[2 * nq][0] = t4[0]; bl[2 * nq][1] = t4[1];
                bl[2 * nq + 1][0] = t4[2]; bl[2 * nq + 1][1] = t4[3];
            }
#pragma unroll
            for (int mi = 0; mi < 2; mi++)
#pragma unroll
                for (int nj = 0; nj < 8; nj++) {
                    MMA16816(acc[mi][nj], ah[mi], bh[nj]);
                    MMA16816(acc[mi][nj], ah[mi], bl[nj]);
                    MMA16816(acc[mi][nj], al[mi], bh[nj]);
                }
        }
        __syncthreads();
    }

    // ---- epilogue: bias + scale, scatter to [B,H,S,64] ----
    const float* bias = (z == 0) ? bq : (z == 1) ? bk : bv;
    float* dst = (z == 0) ? g_q : (z == 1) ? g_k : g_v;
    const float scale = (z == 0) ? 0.125f : 1.0f;
    const int group = lane >> 2, tig = lane & 3;
    const int hh = (n0 + wn * 64) >> 6;                 // head constant per warp
#pragma unroll
    for (int mi = 0; mi < 2; mi++) {
#pragma unroll
        for (int hf = 0; hf < 2; hf++) {
            int m = m0 + wm * 32 + mi * 16 + group + hf * 8;
            int bb = m >> 12, srow = m & (S_ - 1);
            float* o = dst + (((size_t)bb * H_ + hh) * S_ + srow) * DH_;
#pragma unroll
            for (int ni = 0; ni < 8; ni++) {
                int dc = ni * 8 + tig * 2;
                int ng = n0 + wn * 64 + dc;
                float2 w;
                w.x = (acc[mi][ni][2 * hf + 0] + bias[ng])     * scale;
                w.y = (acc[mi][ni][2 * hf + 1] + bias[ng + 1]) * scale;
                *(float2*)&o[dc] = w;
            }
        }
    }
}

// ============================ fp32 helpers (attn) ============================
__device__ __forceinline__ ull pack2(float lo, float hi) {
    ull r; asm("mov.b64 %0, {%1,%2};" : "=l"(r) : "f"(lo), "f"(hi)); return r;
}
__device__ __forceinline__ float2 unpack2(ull u) {
    float2 r; asm("mov.b64 {%0,%1}, %2;" : "=f"(r.x), "=f"(r.y) : "l"(u)); return r;
}
__device__ __forceinline__ void fma2(ull& d, ull a, ull b) {
    asm("fma.rn.f32x2 %0, %1, %2, %0;" : "+l"(d) : "l"(a), "l"(b));
}
__device__ __forceinline__ void mul2(ull& d, ull a) {
    asm("mul.rn.f32x2 %0, %0, %1;" : "+l"(d) : "l"(a));
}
#define NEG_INF (__int_as_float(0xff800000))

// ============================ Banded attention ===============================
#define SMEM_ATTN 204800

__global__ __launch_bounds__(256, 1)
void attn_kernel(const float* __restrict__ att_mask,
                 const unsigned char* __restrict__ idx_mask,
                 float* __restrict__ out)
{
    extern __shared__ char smraw[];
    ull*   Qt2  = (ull*)  (smraw);            // [64][130] dup pairs (d-major)
    float* Kt   = (float*)(smraw + 66560);    // [64][132] (d-major)
    float* Vs   = (float*)(smraw + 100352);   // [128][68] (k-major)
    float* Ps   = (float*)(smraw + 135168);   // [128][132]
    float* fm_s = (float*)(smraw + 202752);   // [128]
    float* m_s  = (float*)(smraw + 203264);
    float* l_s  = (float*)(smraw + 203776);
    float* sc_s = (float*)(smraw + 204288);

    const int tid = threadIdx.x;
    const int tx = tid & 15, ty = tid >> 4;
    const int q0 = blockIdx.x * 128;
    const int b  = blockIdx.y / H_;
    const int h  = blockIdx.y % H_;
    const size_t bh = ((size_t)b * H_ + h) * (size_t)S_ * DH_;

#pragma unroll
    for (int it = 0; it < 8; it++) {
        int idx = it * 256 + tid;
        int qr = idx >> 4, c4 = (idx & 15) * 4;
        float4 v = *(const float4*)&g_q[bh + (size_t)(q0 + qr) * DH_ + c4];
        Qt2[(c4 + 0) * 130 + qr] = pack2(v.x, v.x);
        Qt2[(c4 + 1) * 130 + qr] = pack2(v.y, v.y);
        Qt2[(c4 + 2) * 130 + qr] = pack2(v.z, v.z);
        Qt2[(c4 + 3) * 130 + qr] = pack2(v.w, v.w);
    }
    if (tid < 128) { m_s[tid] = NEG_INF; l_s[tid] = 0.f; }

    ull o2[8][2];
#pragma unroll
    for (int i = 0; i < 8; i++) { o2[i][0] = 0ULL; o2[i][1] = 0ULL; }

    for (int c = 0; c < 5; c++) {
        const int kstart = q0 - 256 + c * 128;
        __syncthreads();

#pragma unroll
        for (int it = 0; it < 8; it++) {
            int idx = it * 256 + tid;
            int kr = idx >> 4, c4 = (idx & 15) * 4;
            int kg = kstart + kr;
            float4 kv = make_float4(0.f, 0.f, 0.f, 0.f);
            float4 vv = make_float4(0.f, 0.f, 0.f, 0.f);
            if ((unsigned)kg < (unsigned)S_) {
                kv = *(const float4*)&g_k[bh + (size_t)kg * DH_ + c4];
                vv = *(const float4*)&g_v[bh + (size_t)kg * DH_ + c4];
            }
            Kt[(c4 + 0) * 132 + kr] = kv.x;
            Kt[(c4 + 1) * 132 + kr] = kv.y;
            Kt[(c4 + 2) * 132 + kr] = kv.z;
            Kt[(c4 + 3) * 132 + kr] = kv.w;
            *(float4*)&Vs[kr * 68 + c4] = vv;
        }
        if (tid < 128) {
            int kg = kstart + tid;
            float fv = NEG_INF;
            if ((unsigned)kg < (unsigned)S_)
                fv = (att_mask[(size_t)b * S_ + kg] != 0.f) ? NEG_INF : 0.f;
            fm_s[tid] = fv;
        }
        __syncthreads();

        // ---- score GEMM ----
        {
            ull sacc[8][4];
#pragma unroll
            for (int i = 0; i < 8; i++)
#pragma unroll
                for (int j = 0; j < 4; j++) sacc[i][j] = 0ULL;

#pragma unroll 16
            for (int d = 0; d < 64; d++) {
                const ulonglong2* pa = (const ulonglong2*)&Qt2[d * 130 + ty * 8];
                ulonglong2 a01 = pa[0], a23 = pa[1], a45 = pa[2], a67 = pa[3];
                const ulonglong2* pb = (const ulonglong2*)&Kt[d * 132 + tx * 8];
                ulonglong2 b01 = pb[0], b23 = pb[1];
                ull av[8] = {a01.x, a01.y, a23.x, a23.y, a45.x, a45.y, a67.x, a67.y};
#pragma unroll
                for (int i = 0; i < 8; i++) {
                    fma2(sacc[i][0], av[i], b01.x);
                    fma2(sacc[i][1], av[i], b01.y);
                    fma2(sacc[i][2], av[i], b23.x);
                    fma2(sacc[i][3], av[i], b23.y);
                }
            }
#pragma unroll
            for (int i = 0; i < 8; i++) {
                float2 s0 = unpack2(sacc[i][0]), s1 = unpack2(sacc[i][1]);
                float2 s2 = unpack2(sacc[i][2]), s3 = unpack2(sacc[i][3]);
                int r = ty * 8 + i, cc = tx * 8;
                *(float4*)&Ps[r * 132 + cc]     = make_float4(s0.x, s0.y, s1.x, s1.y);
                *(float4*)&Ps[r * 132 + cc + 4] = make_float4(s2.x, s2.y, s3.x, s3.y);
            }
        }
        __syncthreads();

        // ---- online softmax: 2 threads per row ----
        {
            int r = tid >> 1, half = tid & 1, cb = half * 64;
            int boff = kstart - q0 + cb - r;
            float mx = NEG_INF;
#pragma unroll
            for (int t = 0; t < 16; t++) {
                float4 sv = *(const float4*)&Ps[r * 132 + cb + t * 4];
                int cc = t * 4; float s;
                s = sv.x + fm_s[cb + cc + 0]; if ((unsigned)(boff + cc + 0 + W_) > 2u * W_) s = NEG_INF; mx = fmaxf(mx, s);
                s = sv.y + fm_s[cb + cc + 1]; if ((unsigned)(boff + cc + 1 + W_) > 2u * W_) s = NEG_INF; mx = fmaxf(mx, s);
                s = sv.z + fm_s[cb + cc + 2]; if ((unsigned)(boff + cc + 2 + W_) > 2u * W_) s = NEG_INF; mx = fmaxf(mx, s);
                s = sv.w + fm_s[cb + cc + 3]; if ((unsigned)(boff + cc + 3 + W_) > 2u * W_) s = NEG_INF; mx = fmaxf(mx, s);
            }
            mx = fmaxf(mx, __shfl_xor_sync(0xffffffffu, mx, 1));
            float m_old = m_s[r];
            float m_new = fmaxf(m_old, mx);
            float scal, mref;
            if (m_new == NEG_INF) { scal = 1.f; mref = 0.f; }
            else                  { scal = __expf(m_old - m_new); mref = m_new; }
            float lsum = 0.f;
#pragma unroll
            for (int t = 0; t < 16; t++) {
                float4 sv = *(float4*)&Ps[r * 132 + cb + t * 4];
                int cc = t * 4; float s, p;
                s = sv.x + fm_s[cb + cc + 0]; if ((unsigned)(boff + cc + 0 + W_) > 2u * W_) s = NEG_INF;
                p = __expf(s - mref); lsum += p; sv.x = p;
                s = sv.y + fm_s[cb + cc + 1]; if ((unsigned)(boff + cc + 1 + W_) > 2u * W_) s = NEG_INF;
                p = __expf(s - mref); lsum += p; sv.y = p;
                s = sv.z + fm_s[cb + cc + 2]; if ((unsigned)(boff + cc + 2 + W_) > 2u * W_) s = NEG_INF;
                p = __expf(s - mref); lsum += p; sv.z = p;
                s = sv.w + fm_s[cb + cc + 3]; if ((unsigned)(boff + cc + 3 + W_) > 2u * W_) s = NEG_INF;
                p = __expf(s - mref); lsum += p; sv.w = p;
                *(float4*)&Ps[r * 132 + cb + t * 4] = sv;
            }
            lsum += __shfl_xor_sync(0xffffffffu, lsum, 1);
            if (half == 0) {
                m_s[r]  = m_new;
                l_s[r]  = l_s[r] * scal + lsum;
                sc_s[r] = scal;
            }
        }
        __syncthreads();

        // ---- rescale + P @ V ----
#pragma unroll
        for (int i = 0; i < 8; i++) {
            float sc = sc_s[ty * 8 + i];
            ull sp = pack2(sc, sc);
            mul2(o2[i][0], sp);
            mul2(o2[i][1], sp);
        }
#pragma unroll 8
        for (int k = 0; k < 128; k++) {
            ulonglong2 vv = *(const ulonglong2*)&Vs[k * 68 + tx * 4];
#pragma unroll
            for (int i = 0; i < 8; i++) {
                float p = Ps[(ty * 8 + i) * 132 + k];
                ull pp = pack2(p, p);
                fma2(o2[i][0], pp, vv.x);
                fma2(o2[i][1], pp, vv.y);
            }
        }
    }

    // ---- epilogue ----
#pragma unroll
    for (int i = 0; i < 8; i++) {
        int r  = ty * 8 + i;
        int qg = q0 + r;
        float inv = 1.f / fmaxf(l_s[r], 1e-37f);
        if (idx_mask[(size_t)b * S_ + qg]) inv = 0.f;
        float2 f0 = unpack2(o2[i][0]);
        float2 f1 = unpack2(o2[i][1]);
        float4 o = make_float4(f0.x * inv, f0.y * inv, f1.x * inv, f1.y * inv);
        *(float4*)&out[((size_t)b * S_ + qg) * D_ + h * DH_ + tx * 4] = o;
    }
}

// =============================================================================
extern "C" void kernel_launch(void* const* d_in, const int* in_sizes, int n_in,
                              void* d_out, int out_size)
{
    const float*         hidden = (const float*)d_in[0];
    const float*         amask  = (const float*)d_in[1];
    const unsigned char* imask  = (const unsigned char*)d_in[2];
    const float* Wq = (const float*)d_in[3];
    const float* bq = (const float*)d_in[4];
    const float* Wk = (const float*)d_in[5];
    const float* bk = (const float*)d_in[6];
    const float* Wv = (const float*)d_in[7];
    const float* bv = (const float*)d_in[8];
    float* out = (float*)d_out;

    cudaFuncSetAttribute(mma_gemm_kernel,
                         cudaFuncAttributeMaxDynamicSharedMemorySize, SM_GEMM);
    cudaFuncSetAttribute(attn_kernel,
                         cudaFuncAttributeMaxDynamicSharedMemorySize, SMEM_ATTN);

    // 1) split-bf16 conversions
    conv_a_kernel<<<(B_ * S_ * D_) / (256 * 4), 256>>>(hidden);
    conv_wt_kernel<<<dim3(D_ / 32, D_ / 32, 3), dim3(32, 8)>>>(Wq, Wk, Wv);

    // 2) warp-MMA projections (Q, K, V via blockIdx.z)
    mma_gemm_kernel<<<dim3(D_ / 128, (B_ * S_) / 128, 3), 256, SM_GEMM>>>(bq, bk, bv);

    // 3) banded attention
    attn_kernel<<<dim3(S_ / 128, B_ * H_), 256, SMEM_ATTN>>>(amask, imask, out);
}

// round 17
// speedup vs baseline: 1.6527x; 1.6514x over previous
#include <cuda_runtime.h>
#include <cuda_bf16.h>
#include <cstdint>

#define B_   2
#define S_   4096
#define D_   768
#define H_   12
#define DH_  64
#define W_   256

typedef unsigned long long ull;

// ------------------------------ device scratch ------------------------------
__device__ __align__(128) float g_v[(size_t)B_ * H_ * S_ * DH_];
__device__ __align__(128) __nv_bfloat16 g_qh[(size_t)B_ * H_ * S_ * DH_];
__device__ __align__(128) __nv_bfloat16 g_ql[(size_t)B_ * H_ * S_ * DH_];
__device__ __align__(128) __nv_bfloat16 g_kh[(size_t)B_ * H_ * S_ * DH_];
__device__ __align__(128) __nv_bfloat16 g_kl[(size_t)B_ * H_ * S_ * DH_];

__device__ __align__(128) __nv_bfloat16 g_Ah[(size_t)B_ * S_ * D_];
__device__ __align__(128) __nv_bfloat16 g_Al[(size_t)B_ * S_ * D_];
__device__ __align__(128) __nv_bfloat16 g_Wth[3 * D_ * D_];   // W^T hi  [n][k]
__device__ __align__(128) __nv_bfloat16 g_Wtl[3 * D_ * D_];   // W^T lo

// ------------------------------ PTX helpers --------------------------------
__device__ __forceinline__ uint32_t smem_u32(const void* p) {
    uint32_t a;
    asm("{ .reg .u64 t; cvta.to.shared.u64 t, %1; cvt.u32.u64 %0, t; }"
        : "=r"(a) : "l"(p));
    return a;
}

#define CP_ASYNC16(dst, src) \
    asm volatile("cp.async.cg.shared.global [%0], [%1], 16;" \
                 :: "r"(dst), "l"(src) : "memory")
#define CP_COMMIT() asm volatile("cp.async.commit_group;" ::: "memory")
#define CP_WAIT0()  asm volatile("cp.async.wait_group 0;" ::: "memory")
#define CP_WAIT1()  asm volatile("cp.async.wait_group 1;" ::: "memory")

#define LDSM4(r, a) \
    asm volatile("ldmatrix.sync.aligned.m8n8.x4.shared.b16 {%0,%1,%2,%3}, [%4];" \
                 : "=r"((r)[0]), "=r"((r)[1]), "=r"((r)[2]), "=r"((r)[3]) : "r"(a))

#define MMA16816(d, a, b0v, b1v) \
    asm volatile("mma.sync.aligned.m16n8k16.row.col.f32.bf16.bf16.f32 " \
                 "{%0,%1,%2,%3}, {%4,%5,%6,%7}, {%8,%9}, {%0,%1,%2,%3};" \
                 : "+f"((d)[0]), "+f"((d)[1]), "+f"((d)[2]), "+f"((d)[3]) \
                 : "r"((a)[0]), "r"((a)[1]), "r"((a)[2]), "r"((a)[3]), \
                   "r"(b0v), "r"(b1v))

#define NEG_INF (__int_as_float(0xff800000))

// =========================== convert: A -> hi/lo bf16 ========================
__global__ __launch_bounds__(256)
void conv_a_kernel(const float* __restrict__ A)
{
    size_t i = ((size_t)blockIdx.x * 256 + threadIdx.x) * 4;
    float4 v = *(const float4*)&A[i];
    __nv_bfloat16 h0 = __float2bfloat16(v.x);
    __nv_bfloat16 h1 = __float2bfloat16(v.y);
    __nv_bfloat16 h2 = __float2bfloat16(v.z);
    __nv_bfloat16 h3 = __float2bfloat16(v.w);
    __nv_bfloat16 l0 = __float2bfloat16(v.x - __bfloat162float(h0));
    __nv_bfloat16 l1 = __float2bfloat16(v.y - __bfloat162float(h1));
    __nv_bfloat16 l2 = __float2bfloat16(v.z - __bfloat162float(h2));
    __nv_bfloat16 l3 = __float2bfloat16(v.w - __bfloat162float(h3));
    *(__nv_bfloat162*)&g_Ah[i]     = __nv_bfloat162(h0, h1);
    *(__nv_bfloat162*)&g_Ah[i + 2] = __nv_bfloat162(h2, h3);
    *(__nv_bfloat162*)&g_Al[i]     = __nv_bfloat162(l0, l1);
    *(__nv_bfloat162*)&g_Al[i + 2] = __nv_bfloat162(l2, l3);
}

// ==================== convert: W -> W^T hi/lo bf16 (tiled) ===================
__global__ __launch_bounds__(256)
void conv_wt_kernel(const float* __restrict__ Wq, const float* __restrict__ Wk,
                    const float* __restrict__ Wv)
{
    __shared__ float t[32][33];
    const int z = blockIdx.z;
    const float* Wm = (z == 0) ? Wq : (z == 1) ? Wk : Wv;
    const int n0 = blockIdx.x * 32, k0 = blockIdx.y * 32;
    const int tx = threadIdx.x, ty = threadIdx.y;   // (32, 8)
#pragma unroll
    for (int j = 0; j < 4; j++)
        t[ty + 8 * j][tx] = Wm[(size_t)(k0 + ty + 8 * j) * D_ + n0 + tx];
    __syncthreads();
    size_t base = (size_t)z * D_ * D_;
#pragma unroll
    for (int j = 0; j < 4; j++) {
        int n = n0 + ty + 8 * j, k = k0 + tx;
        float x = t[tx][ty + 8 * j];
        __nv_bfloat16 hi = __float2bfloat16(x);
        __nv_bfloat16 lo = __float2bfloat16(x - __bfloat162float(hi));
        g_Wth[base + (size_t)n * D_ + k] = hi;
        g_Wtl[base + (size_t)n * D_ + k] = lo;
    }
}

// ================= warp-MMA split-bf16 projection GEMM ======================
#define TILE_B   18432              // 128*72*2
#define BUF_B    (4 * TILE_B)
#define SM_GEMM  (2 * BUF_B)

__global__ __launch_bounds__(256, 1)
void mma_gemm_kernel(const float* __restrict__ bq, const float* __restrict__ bk,
                     const float* __restrict__ bv)
{
    extern __shared__ char sm[];
    const uint32_t smb = smem_u32(sm);
    const int tid  = threadIdx.x;
    const int wid  = tid >> 5, lane = tid & 31;
    const int wm   = wid & 3,  wn   = wid >> 2;     // warp grid 4 x 2
    const int n0   = blockIdx.x * 128;
    const int m0   = blockIdx.y * 128;
    const int z    = blockIdx.z;

    const __nv_bfloat16* __restrict__ Wth = g_Wth + (size_t)z * D_ * D_;
    const __nv_bfloat16* __restrict__ Wtl = g_Wtl + (size_t)z * D_ * D_;

    const uint32_t a_off = (uint32_t)((wm * 32 + (lane & 15)) * 144 +
                                      ((lane >> 4) << 4));
    const uint32_t b_off = (uint32_t)((wn * 64 + ((lane >> 4) << 3) + (lane & 7)) * 144 +
                                      ((lane & 8) << 1));

    float acc[2][8][4];
#pragma unroll
    for (int mi = 0; mi < 2; mi++)
#pragma unroll
        for (int ni = 0; ni < 8; ni++)
#pragma unroll
            for (int r = 0; r < 4; r++) acc[mi][ni][r] = 0.f;

#pragma unroll
    for (int it = 0; it < 4; it++) {
        int idx = it * 256 + tid;
        int r = idx >> 3, c = (idx & 7) * 8;
        uint32_t so = (uint32_t)(r * 144 + c * 2);
        size_t ga = (size_t)(m0 + r) * D_ + c;
        size_t gb = (size_t)(n0 + r) * D_ + c;
        CP_ASYNC16(smb + 0 * TILE_B + so, (const char*)&g_Ah[ga]);
        CP_ASYNC16(smb + 1 * TILE_B + so, (const char*)&g_Al[ga]);
        CP_ASYNC16(smb + 2 * TILE_B + so, (const char*)&Wth[gb]);
        CP_ASYNC16(smb + 3 * TILE_B + so, (const char*)&Wtl[gb]);
    }
    CP_COMMIT();

    for (int p = 0; p < 12; p++) {
        const uint32_t buf = smb + (p & 1) * BUF_B;
        if (p < 11) {
            const uint32_t nb = smb + ((p + 1) & 1) * BUF_B;
            const int kt = (p + 1) * 64;
#pragma unroll
            for (int it = 0; it < 4; it++) {
                int idx = it * 256 + tid;
                int r = idx >> 3, c = (idx & 7) * 8;
                uint32_t so = (uint32_t)(r * 144 + c * 2);
                size_t ga = (size_t)(m0 + r) * D_ + kt + c;
                size_t gb = (size_t)(n0 + r) * D_ + kt + c;
                CP_ASYNC16(nb + 0 * TILE_B + so, (const char*)&g_Ah[ga]);
                CP_ASYNC16(nb + 1 * TILE_B + so, (const char*)&g_Al[ga]);
                CP_ASYNC16(nb + 2 * TILE_B + so, (const char*)&Wth[gb]);
                CP_ASYNC16(nb + 3 * TILE_B + so, (const char*)&Wtl[gb]);
            }
            CP_COMMIT();
            CP_WAIT1();
        } else {
            CP_WAIT0();
        }
        __syncthreads();

#pragma unroll
        for (int kk = 0; kk < 4; kk++) {
            const uint32_t kb = kk * 32;
            uint32_t ah[2][4], al[2][4];
#pragma unroll
            for (int mi = 0; mi < 2; mi++) {
                LDSM4(ah[mi], buf + 0 * TILE_B + a_off + mi * 2304 + kb);
                LDSM4(al[mi], buf + 1 * TILE_B + a_off + mi * 2304 + kb);
            }
            uint32_t bh[8][2], bl[8][2];
#pragma unroll
            for (int nq = 0; nq < 4; nq++) {
                uint32_t t4[4];
                LDSM4(t4, buf + 2 * TILE_B + b_off + nq * 2304 + kb);
                bh[2 * nq][0] = t4[0]; bh[2 * nq][1] = t4[1];
                bh[2 * nq + 1][0] = t4[2]; bh[2 * nq + 1][1] = t4[3];
                LDSM4(t4, buf + 3 * TILE_B + b_off + nq * 2304 + kb);
                bl[2 * nq][0] = t4[0]; bl[2 * nq][1] = t4[1];
                bl[2 * nq + 1][0] = t4[2]; bl[2 * nq + 1][1] = t4[3];
            }
#pragma unroll
            for (int mi = 0; mi < 2; mi++)
#pragma unroll
                for (int nj = 0; nj < 8; nj++) {
                    MMA16816(acc[mi][nj], ah[mi], bh[nj][0], bh[nj][1]);
                    MMA16816(acc[mi][nj], ah[mi], bl[nj][0], bl[nj][1]);
                    MMA16816(acc[mi][nj], al[mi], bh[nj][0], bh[nj][1]);
                }
        }
        __syncthreads();
    }

    // ---- epilogue: bias + scale; Q/K -> bf16 hi/lo, V -> fp32 ----
    const float* bias = (z == 0) ? bq : (z == 1) ? bk : bv;
    const float scale = (z == 0) ? 0.125f : 1.0f;
    const int tig = lane & 3;
    const int hh = (n0 + wn * 64) >> 6;
#pragma unroll
    for (int mi = 0; mi < 2; mi++) {
#pragma unroll
        for (int hf = 0; hf < 2; hf++) {
            int m = m0 + wm * 32 + mi * 16 + (lane >> 2) + hf * 8;
            int bb = m >> 12, srow = m & (S_ - 1);
            size_t base = (((size_t)bb * H_ + hh) * S_ + srow) * DH_;
            if (z == 2) {
                float* o = g_v + base;
#pragma unroll
                for (int ni = 0; ni < 8; ni++) {
                    int dc = ni * 8 + tig * 2;
                    int ng = n0 + wn * 64 + dc;
                    float2 wv;
                    wv.x = acc[mi][ni][2 * hf + 0] + bias[ng];
                    wv.y = acc[mi][ni][2 * hf + 1] + bias[ng + 1];
                    *(float2*)&o[dc] = wv;
                }
            } else {
                __nv_bfloat16* oh = ((z == 0) ? g_qh : g_kh) + base;
                __nv_bfloat16* ol = ((z == 0) ? g_ql : g_kl) + base;
#pragma unroll
                for (int ni = 0; ni < 8; ni++) {
                    int dc = ni * 8 + tig * 2;
                    int ng = n0 + wn * 64 + dc;
                    float x = (acc[mi][ni][2 * hf + 0] + bias[ng])     * scale;
                    float y = (acc[mi][ni][2 * hf + 1] + bias[ng + 1]) * scale;
                    __nv_bfloat162 h2 = __floats2bfloat162_rn(x, y);
                    __nv_bfloat162 l2 = __floats2bfloat162_rn(
                        x - __bfloat162float(h2.x), y - __bfloat162float(h2.y));
                    *(__nv_bfloat162*)&oh[dc] = h2;
                    *(__nv_bfloat162*)&ol[dc] = l2;
                }
            }
        }
    }
}

// ===================== tensor-core banded attention ==========================
// smem layout (bytes)
#define SQH  0
#define SQL  18432
#define SKH  36864
#define SKL  55296
#define SVH  73728      // Vt hi [64][136] bf16
#define SVL  91136
#define SFM  108544
#define SMEM_ATTN 109056

__global__ __launch_bounds__(256, 1)
void attn_kernel(const float* __restrict__ att_mask,
                 const unsigned char* __restrict__ idx_mask,
                 float* __restrict__ out)
{
    extern __shared__ char sm[];
    const uint32_t smb = smem_u32(sm);
    __nv_bfloat16* Vh = (__nv_bfloat16*)(sm + SVH);
    __nv_bfloat16* Vl = (__nv_bfloat16*)(sm + SVL);
    float* fm = (float*)(sm + SFM);

    const int tid = threadIdx.x, lane = tid & 31, w = tid >> 5;
    const int q0 = blockIdx.x * 128;
    const int b  = blockIdx.y / H_;
    const int h  = blockIdx.y % H_;
    const size_t bho = ((size_t)b * H_ + h) * (size_t)S_ * DH_;

    // ---- load Q tiles once (bf16 hi/lo, 144B rows) ----
#pragma unroll
    for (int it = 0; it < 4; it++) {
        int idx = it * 256 + tid;
        int r = idx >> 3, c8 = idx & 7;
        size_t ga = bho + (size_t)(q0 + r) * DH_ + c8 * 8;
        *(uint4*)(sm + SQH + r * 144 + c8 * 16) = *(const uint4*)&g_qh[ga];
        *(uint4*)(sm + SQL + r * 144 + c8 * 16) = *(const uint4*)&g_ql[ga];
    }

    const uint32_t a_off  = (uint32_t)((w * 16 + (lane & 15)) * 144 + ((lane >> 4) << 4));
    const uint32_t bk_off = (uint32_t)((((lane >> 4) << 3) + (lane & 7)) * 144 + ((lane & 8) << 1));
    const uint32_t bv_off = (uint32_t)((((lane >> 4) << 3) + (lane & 7)) * 272 + ((lane & 8) << 1));

    const int rl0 = w * 16 + (lane >> 2);   // local q rows owned by this thread
    float m0 = NEG_INF, m1 = NEG_INF, l0 = 0.f, l1 = 0.f;
    float oacc[8][4];
#pragma unroll
    for (int j = 0; j < 8; j++)
#pragma unroll
        for (int r = 0; r < 4; r++) oacc[j][r] = 0.f;

    const int vrow = tid & 127, vcg = tid >> 7;

    for (int c = 0; c < 5; c++) {
        const int kstart = q0 - 256 + c * 128;
        __syncthreads();

        // ---- K tiles (bf16 hi/lo), zero out-of-range rows ----
        const uint4 z4 = make_uint4(0u, 0u, 0u, 0u);
#pragma unroll
        for (int it = 0; it < 4; it++) {
            int idx = it * 256 + tid;
            int r = idx >> 3, c8 = idx & 7;
            int kg = kstart + r;
            uint4 vh_ = z4, vl_ = z4;
            if ((unsigned)kg < (unsigned)S_) {
                size_t ga = bho + (size_t)kg * DH_ + c8 * 8;
                vh_ = *(const uint4*)&g_kh[ga];
                vl_ = *(const uint4*)&g_kl[ga];
            }
            *(uint4*)(sm + SKH + r * 144 + c8 * 16) = vh_;
            *(uint4*)(sm + SKL + r * 144 + c8 * 16) = vl_;
        }
        // ---- V transpose + split: Vt[d][key], 272B rows ----
        {
            int kg = kstart + vrow;
            bool ok = (unsigned)kg < (unsigned)S_;
            const float* vsrc = &g_v[bho + (size_t)kg * DH_];
#pragma unroll
            for (int g2 = 0; g2 < 8; g2++) {
                int c4 = (vcg + 2 * g2) * 4;
                float4 vv = ok ? *(const float4*)&vsrc[c4]
                               : make_float4(0.f, 0.f, 0.f, 0.f);
                float va[4] = {vv.x, vv.y, vv.z, vv.w};
#pragma unroll
                for (int j = 0; j < 4; j++) {
                    __nv_bfloat16 hi = __float2bfloat16(va[j]);
                    __nv_bfloat16 lo = __float2bfloat16(va[j] - __bfloat162float(hi));
                    Vh[(c4 + j) * 136 + vrow] = hi;
                    Vl[(c4 + j) * 136 + vrow] = lo;
                }
            }
        }
        if (tid < 128) {
            int kg = kstart + tid;
            float fv = NEG_INF;
            if ((unsigned)kg < (unsigned)S_)
                fv = (att_mask[(size_t)b * S_ + kg] != 0.f) ? NEG_INF : 0.f;
            fm[tid] = fv;
        }
        __syncthreads();

        // ---- score GEMM: S[16q x 128k] per warp ----
        float sacc[16][4];
#pragma unroll
        for (int j = 0; j < 16; j++)
#pragma unroll
            for (int r = 0; r < 4; r++) sacc[j][r] = 0.f;

#pragma unroll
        for (int kb = 0; kb < 4; kb++) {
            uint32_t ah[4], al[4];
            LDSM4(ah, smb + SQH + a_off + kb * 32);
            LDSM4(al, smb + SQL + a_off + kb * 32);
#pragma unroll
            for (int nq = 0; nq < 8; nq++) {
                uint32_t kh4[4], kl4[4];
                LDSM4(kh4, smb + SKH + bk_off + nq * 2304 + kb * 32);
                LDSM4(kl4, smb + SKL + bk_off + nq * 2304 + kb * 32);
                MMA16816(sacc[2 * nq],     ah, kh4[0], kh4[1]);
                MMA16816(sacc[2 * nq],     ah, kl4[0], kl4[1]);
                MMA16816(sacc[2 * nq],     al, kh4[0], kh4[1]);
                MMA16816(sacc[2 * nq + 1], ah, kh4[2], kh4[3]);
                MMA16816(sacc[2 * nq + 1], ah, kl4[2], kl4[3]);
                MMA16816(sacc[2 * nq + 1], al, kh4[2], kh4[3]);
            }
        }

        // ---- mask + online softmax (registers + quad shuffles) ----
        const int boff0 = kstart - q0 - rl0 + 256;  // valid iff boff0+lc in [0,512]
        const int boff1 = boff0 - 8;
        float mx0 = NEG_INF, mx1 = NEG_INF;
#pragma unroll
        for (int j = 0; j < 16; j++) {
            int lc = 8 * j + 2 * (lane & 3);
            float f0 = fm[lc], f1 = fm[lc + 1];
            float s;
            s = sacc[j][0] + f0; if ((unsigned)(boff0 + lc)     > 512u) s = NEG_INF; sacc[j][0] = s; mx0 = fmaxf(mx0, s);
            s = sacc[j][1] + f1; if ((unsigned)(boff0 + lc + 1) > 512u) s = NEG_INF; sacc[j][1] = s; mx0 = fmaxf(mx0, s);
            s = sacc[j][2] + f0; if ((unsigned)(boff1 + lc)     > 512u) s = NEG_INF; sacc[j][2] = s; mx1 = fmaxf(mx1, s);
            s = sacc[j][3] + f1; if ((unsigned)(boff1 + lc + 1) > 512u) s = NEG_INF; sacc[j][3] = s; mx1 = fmaxf(mx1, s);
        }
        mx0 = fmaxf(mx0, __shfl_xor_sync(0xffffffffu, mx0, 1));
        mx0 = fmaxf(mx0, __shfl_xor_sync(0xffffffffu, mx0, 2));
        mx1 = fmaxf(mx1, __shfl_xor_sync(0xffffffffu, mx1, 1));
        mx1 = fmaxf(mx1, __shfl_xor_sync(0xffffffffu, mx1, 2));

        float mn0 = fmaxf(m0, mx0), mn1 = fmaxf(m1, mx1);
        float scal0, mr0, scal1, mr1;
        if (mn0 == NEG_INF) { scal0 = 1.f; mr0 = 0.f; }
        else                { scal0 = __expf(m0 - mn0); mr0 = mn0; }
        if (mn1 == NEG_INF) { scal1 = 1.f; mr1 = 0.f; }
        else                { scal1 = __expf(m1 - mn1); mr1 = mn1; }
        m0 = mn0; m1 = mn1;

        float ls0 = 0.f, ls1 = 0.f;
#pragma unroll
        for (int j = 0; j < 16; j++) {
            float p;
            p = __expf(sacc[j][0] - mr0); ls0 += p; sacc[j][0] = p;
            p = __expf(sacc[j][1] - mr0); ls0 += p; sacc[j][1] = p;
            p = __expf(sacc[j][2] - mr1); ls1 += p; sacc[j][2] = p;
            p = __expf(sacc[j][3] - mr1); ls1 += p; sacc[j][3] = p;
        }
        ls0 += __shfl_xor_sync(0xffffffffu, ls0, 1);
        ls0 += __shfl_xor_sync(0xffffffffu, ls0, 2);
        ls1 += __shfl_xor_sync(0xffffffffu, ls1, 1);
        ls1 += __shfl_xor_sync(0xffffffffu, ls1, 2);
        l0 = l0 * scal0 + ls0;
        l1 = l1 * scal1 + ls1;

#pragma unroll
        for (int j = 0; j < 8; j++) {
            oacc[j][0] *= scal0; oacc[j][1] *= scal0;
            oacc[j][2] *= scal1; oacc[j][3] *= scal1;
        }

        // ---- P @ V (split P into hi/lo, reuse as A fragments) ----
#pragma unroll
        for (int kk = 0; kk < 8; kk++) {
            uint32_t ph[4], pl[4];
#pragma unroll
            for (int q = 0; q < 4; q++) {
                const float x = (q < 2) ? sacc[2 * kk][2 * q]     : sacc[2 * kk + 1][2 * (q - 2)];
                const float y = (q < 2) ? sacc[2 * kk][2 * q + 1] : sacc[2 * kk + 1][2 * (q - 2) + 1];
                __nv_bfloat162 h2 = __floats2bfloat162_rn(x, y);
                __nv_bfloat162 l2 = __floats2bfloat162_rn(
                    x - __bfloat162float(h2.x), y - __bfloat162float(h2.y));
                ph[q] = *(uint32_t*)&h2;
                pl[q] = *(uint32_t*)&l2;
            }
#pragma unroll
            for (int nq = 0; nq < 4; nq++) {
                uint32_t vh4[4], vl4[4];
                LDSM4(vh4, smb + SVH + bv_off + nq * 4352 + kk * 32);
                LDSM4(vl4, smb + SVL + bv_off + nq * 4352 + kk * 32);
                MMA16816(oacc[2 * nq],     ph, vh4[0], vh4[1]);
                MMA16816(oacc[2 * nq],     ph, vl4[0], vl4[1]);
                MMA16816(oacc[2 * nq],     pl, vh4[0], vh4[1]);
                MMA16816(oacc[2 * nq + 1], ph, vh4[2], vh4[3]);
                MMA16816(oacc[2 * nq + 1], ph, vl4[2], vl4[3]);
                MMA16816(oacc[2 * nq + 1], pl, vh4[2], vh4[3]);
            }
        }
    }

    // ---- epilogue ----
    const int qg0 = q0 + rl0, qg1 = qg0 + 8;
    float inv0 = 1.f / fmaxf(l0, 1e-37f);
    float inv1 = 1.f / fmaxf(l1, 1e-37f);
    if (idx_mask[(size_t)b * S_ + qg0]) inv0 = 0.f;
    if (idx_mask[(size_t)b * S_ + qg1]) inv1 = 0.f;
    float* o0 = &out[((size_t)b * S_ + qg0) * D_ + h * DH_];
    float* o1 = &out[((size_t)b * S_ + qg1) * D_ + h * DH_];
#pragma unroll
    for (int j = 0; j < 8; j++) {
        int dc = 8 * j + 2 * (lane & 3);
        *(float2*)&o0[dc] = make_float2(oacc[j][0] * inv0, oacc[j][1] * inv0);
        *(float2*)&o1[dc] = make_float2(oacc[j][2] * inv1, oacc[j][3] * inv1);
    }
}

// =============================================================================
extern "C" void kernel_launch(void* const* d_in, const int* in_sizes, int n_in,
                              void* d_out, int out_size)
{
    const float*         hidden = (const float*)d_in[0];
    const float*         amask  = (const float*)d_in[1];
    const unsigned char* imask  = (const unsigned char*)d_in[2];
    const float* Wq = (const float*)d_in[3];
    const float* bq = (const float*)d_in[4];
    const float* Wk = (const float*)d_in[5];
    const float* bk = (const float*)d_in[6];
    const float* Wv = (const float*)d_in[7];
    const float* bv = (const float*)d_in[8];
    float* out = (float*)d_out;

    cudaFuncSetAttribute(mma_gemm_kernel,
                         cudaFuncAttributeMaxDynamicSharedMemorySize, SM_GEMM);
    cudaFuncSetAttribute(attn_kernel,
                         cudaFuncAttributeMaxDynamicSharedMemorySize, SMEM_ATTN);

    conv_a_kernel<<<(B_ * S_ * D_) / (256 * 4), 256>>>(hidden);
    conv_wt_kernel<<<dim3(D_ / 32, D_ / 32, 3), dim3(32, 8)>>>(Wq, Wk, Wv);

    mma_gemm_kernel<<<dim3(D_ / 128, (B_ * S_) / 128, 3), 256, SM_GEMM>>>(bq, bk, bv);

    attn_kernel<<<dim3(S_ / 128, B_ * H_), 256, SMEM_ATTN>>>(amask, imask, out);
}